// round 10
// baseline (speedup 1.0000x reference)
#include <cuda_runtime.h>
#include <math.h>
#include <stdint.h>

#define NN   50000
#define NE   800000
#define DIM  512
#define NOUT 40
#define BN_EPS 1e-5f
#define NPB  512   // BN partial blocks

// ---------------- device scratch (module-static, allowed) ----------------
__device__ __align__(16) int   g_cnt[NN];
__device__ __align__(16) int   g_fill[NN];
__device__ __align__(16) int   g_rowptr[NN + 1];
__device__ __align__(16) float g_dis[NN];
__device__ __align__(16) int   g_col[NE];
__device__ __align__(16) float g_h   [NN * DIM];   // GEMM output
__device__ __align__(16) float g_agg1[NN * DIM];   // raw agg, layer 1
__device__ __align__(16) float g_agg2[NN * DIM];   // raw agg, layer 2
__device__ __align__(16) float g_agg3[NN * DIM];   // raw agg, layer 3 (= x3)
__device__ __align__(16) float g_psum[NPB * DIM];
__device__ __align__(16) float g_psq [NPB * DIM];
__device__ __align__(16) float g_sc1[DIM], g_sh1[DIM];
__device__ __align__(16) float g_sc2[DIM], g_sh2[DIM];

// ---------------- graph preprocessing ----------------
__global__ void k_zero_cnt() {
    int i = blockIdx.x * blockDim.x + threadIdx.x;
    if (i < NN) { g_cnt[i] = 0; g_fill[i] = 0; }
}

__global__ void k_count(const int* __restrict__ dst) {
    int e = blockIdx.x * blockDim.x + threadIdx.x;
    if (e < NE) atomicAdd(&g_cnt[dst[e]], 1);
}

// single-block inclusive scan -> rowptr, and dis = rsqrt(deg) with self-loop
// warp-shuffle scan + warp-sums scan: 4 barriers per 1024-tile
__global__ __launch_bounds__(1024) void k_scan() {
    __shared__ int warp_sums[32];
    __shared__ int s_running;
    const int tid  = threadIdx.x;
    const int lane = tid & 31;
    const int wid  = tid >> 5;
    if (tid == 0) { g_rowptr[0] = 0; s_running = 0; }
    __syncthreads();
    for (int base = 0; base < NN; base += 1024) {
        int i = base + tid;
        int v = (i < NN) ? g_cnt[i] : 0;
        if (i < NN) g_dis[i] = rsqrtf((float)(v + 1));  // +1 self-loop
        int x = v;
        #pragma unroll
        for (int off = 1; off < 32; off <<= 1) {
            int y = __shfl_up_sync(0xFFFFFFFFu, x, off);
            if (lane >= off) x += y;
        }
        if (lane == 31) warp_sums[wid] = x;
        __syncthreads();
        if (wid == 0) {
            int w = warp_sums[lane];
            #pragma unroll
            for (int off = 1; off < 32; off <<= 1) {
                int y = __shfl_up_sync(0xFFFFFFFFu, w, off);
                if (lane >= off) w += y;
            }
            warp_sums[lane] = w;
        }
        __syncthreads();
        int warp_off = (wid > 0) ? warp_sums[wid - 1] : 0;
        int incl = x + warp_off + s_running;
        if (i < NN) g_rowptr[i + 1] = incl;
        __syncthreads();
        if (tid == 1023) s_running = incl;
        __syncthreads();
    }
}

__global__ void k_fill(const int* __restrict__ src, const int* __restrict__ dst) {
    int e = blockIdx.x * blockDim.x + threadIdx.x;
    if (e < NE) {
        int d = dst[e];
        int p = g_rowptr[d] + atomicAdd(&g_fill[d], 1);
        g_col[p] = src[e];
    }
}

// per-node insertion sort of adjacency row -> g_col deterministic regardless of
// atomic fill order -> bitwise-stable fp sums downstream
__global__ void k_sortadj() {
    int n = blockIdx.x * blockDim.x + threadIdx.x;
    if (n >= NN) return;
    int beg = g_rowptr[n], end = g_rowptr[n + 1];
    for (int i = beg + 1; i < end; ++i) {
        int key = g_col[i];
        int j = i - 1;
        while (j >= beg && g_col[j] > key) { g_col[j + 1] = g_col[j]; --j; }
        g_col[j + 1] = key;
    }
}

// ---------------- tf32 helpers ----------------
// cvt.rna.tf32.f32 requires .b32 dest -> "=r" constraint (NOT "=f")
__device__ __forceinline__ float f2tf32(float x) {
    uint32_t r;
    asm("cvt.rna.tf32.f32 %0, %1;" : "=r"(r) : "f"(x));
    return __uint_as_float(r);
}

__device__ __forceinline__ void mma_tf32(float& c0, float& c1, float& c2, float& c3,
                                         float a0, float a1, float a2, float a3,
                                         float b0, float b1) {
    asm volatile(
        "mma.sync.aligned.m16n8k8.row.col.f32.tf32.tf32.f32 "
        "{%0,%1,%2,%3}, {%4,%5,%6,%7}, {%8,%9}, {%0,%1,%2,%3};"
        : "+f"(c0), "+f"(c1), "+f"(c2), "+f"(c3)
        : "r"(__float_as_uint(a0)), "r"(__float_as_uint(a1)),
          "r"(__float_as_uint(a2)), "r"(__float_as_uint(a3)),
          "r"(__float_as_uint(b0)), "r"(__float_as_uint(b1)));
}

__device__ __forceinline__ float4 bnrelu4(float4 v, float4 sc, float4 sh) {
    v.x = fmaxf(fmaf(v.x, sc.x, sh.x), 0.f);
    v.y = fmaxf(fmaf(v.y, sc.y, sh.y), 0.f);
    v.z = fmaxf(fmaf(v.z, sc.z, sh.z), 0.f);
    v.w = fmaxf(fmaf(v.w, sc.w, sh.w), 0.f);
    return v;
}

// ---------------- tf32 tensor-core GEMM: C[M,512] = f(A)[M,512] @ B[512,512] ----------------
// BN template: f(A) = relu(A*sc + sh) applied at load (per-feature = per-k)
// block 128x128, Ktile 16, double-buffered; 8 warps, each 32(M) x 64(N)
#define SPAD 136
template <int BN>
__global__ __launch_bounds__(256) void k_gemm_tf32(const float* __restrict__ A,
                                                   const float* __restrict__ B,
                                                   float* __restrict__ C,
                                                   const float* __restrict__ sc,
                                                   const float* __restrict__ sh) {
    __shared__ float As[2][16][SPAD];   // [k][m]
    __shared__ float Bs[2][16][SPAD];   // [k][n]
    const int tid  = threadIdx.x;
    const int crow = blockIdx.y * 128;
    const int ccol = blockIdx.x * 128;

    const int warp = tid >> 5;
    const int lane = tid & 31;
    const int g    = lane >> 2;      // groupID 0..7
    const int tig  = lane & 3;       // thread-in-group 0..3
    const int wm   = (warp & 3) * 32;  // warp M offset 0..96
    const int wn   = (warp >> 2) * 64; // warp N offset 0,64

    const int aRow = tid >> 1;             // 0..127
    const int aK   = (tid & 1) * 8;        // 0 or 8
    const int bRow = tid >> 4;             // 0..15
    const int bC   = (tid & 15) * 4;       // 0..60, +64 for second

    float acc[2][8][4];
    #pragma unroll
    for (int mt = 0; mt < 2; mt++)
        #pragma unroll
        for (int nt = 0; nt < 8; nt++)
            #pragma unroll
            for (int i = 0; i < 4; i++) acc[mt][nt][i] = 0.f;

    const float4 z4 = make_float4(0.f, 0.f, 0.f, 0.f);
    float4 va0, va1, vb0, vb1;

    // ---- prologue: load K-tile 0 ----
    {
        int r = crow + aRow;
        va0 = (r < NN) ? *(const float4*)(A + (size_t)r * 512 + 0 + aK)     : z4;
        va1 = (r < NN) ? *(const float4*)(A + (size_t)r * 512 + 0 + aK + 4) : z4;
        if (BN) {
            va0 = bnrelu4(va0, *(const float4*)(sc + aK),     *(const float4*)(sh + aK));
            va1 = bnrelu4(va1, *(const float4*)(sc + aK + 4), *(const float4*)(sh + aK + 4));
        }
        vb0 = *(const float4*)(B + (size_t)(0 + bRow) * 512 + ccol + bC);
        vb1 = *(const float4*)(B + (size_t)(0 + bRow) * 512 + ccol + bC + 64);
        As[0][aK + 0][aRow] = f2tf32(va0.x);
        As[0][aK + 1][aRow] = f2tf32(va0.y);
        As[0][aK + 2][aRow] = f2tf32(va0.z);
        As[0][aK + 3][aRow] = f2tf32(va0.w);
        As[0][aK + 4][aRow] = f2tf32(va1.x);
        As[0][aK + 5][aRow] = f2tf32(va1.y);
        As[0][aK + 6][aRow] = f2tf32(va1.z);
        As[0][aK + 7][aRow] = f2tf32(va1.w);
        *(float4*)&Bs[0][bRow][bC] =
            make_float4(f2tf32(vb0.x), f2tf32(vb0.y), f2tf32(vb0.z), f2tf32(vb0.w));
        *(float4*)&Bs[0][bRow][bC + 64] =
            make_float4(f2tf32(vb1.x), f2tf32(vb1.y), f2tf32(vb1.z), f2tf32(vb1.w));
    }
    __syncthreads();

    int buf = 0;
    for (int t = 0; t < 32; ++t) {
        if (t < 31) {
            const int k0 = (t + 1) * 16;
            int r = crow + aRow;
            va0 = (r < NN) ? *(const float4*)(A + (size_t)r * 512 + k0 + aK)     : z4;
            va1 = (r < NN) ? *(const float4*)(A + (size_t)r * 512 + k0 + aK + 4) : z4;
            if (BN) {
                va0 = bnrelu4(va0, *(const float4*)(sc + k0 + aK),     *(const float4*)(sh + k0 + aK));
                va1 = bnrelu4(va1, *(const float4*)(sc + k0 + aK + 4), *(const float4*)(sh + k0 + aK + 4));
            }
            vb0 = *(const float4*)(B + (size_t)(k0 + bRow) * 512 + ccol + bC);
            vb1 = *(const float4*)(B + (size_t)(k0 + bRow) * 512 + ccol + bC + 64);
        }
        #pragma unroll
        for (int kk = 0; kk < 16; kk += 8) {
            float af[2][4];
            #pragma unroll
            for (int mt = 0; mt < 2; mt++) {
                int m = wm + mt * 16 + g;
                af[mt][0] = As[buf][kk + tig]    [m];
                af[mt][1] = As[buf][kk + tig]    [m + 8];
                af[mt][2] = As[buf][kk + tig + 4][m];
                af[mt][3] = As[buf][kk + tig + 4][m + 8];
            }
            float bfr[8][2];
            #pragma unroll
            for (int nt = 0; nt < 8; nt++) {
                int n = wn + nt * 8 + g;
                bfr[nt][0] = Bs[buf][kk + tig]    [n];
                bfr[nt][1] = Bs[buf][kk + tig + 4][n];
            }
            #pragma unroll
            for (int mt = 0; mt < 2; mt++)
                #pragma unroll
                for (int nt = 0; nt < 8; nt++)
                    mma_tf32(acc[mt][nt][0], acc[mt][nt][1], acc[mt][nt][2], acc[mt][nt][3],
                             af[mt][0], af[mt][1], af[mt][2], af[mt][3],
                             bfr[nt][0], bfr[nt][1]);
        }
        if (t < 31) {
            int nb = buf ^ 1;
            As[nb][aK + 0][aRow] = f2tf32(va0.x);
            As[nb][aK + 1][aRow] = f2tf32(va0.y);
            As[nb][aK + 2][aRow] = f2tf32(va0.z);
            As[nb][aK + 3][aRow] = f2tf32(va0.w);
            As[nb][aK + 4][aRow] = f2tf32(va1.x);
            As[nb][aK + 5][aRow] = f2tf32(va1.y);
            As[nb][aK + 6][aRow] = f2tf32(va1.z);
            As[nb][aK + 7][aRow] = f2tf32(va1.w);
            *(float4*)&Bs[nb][bRow][bC] =
                make_float4(f2tf32(vb0.x), f2tf32(vb0.y), f2tf32(vb0.z), f2tf32(vb0.w));
            *(float4*)&Bs[nb][bRow][bC + 64] =
                make_float4(f2tf32(vb1.x), f2tf32(vb1.y), f2tf32(vb1.z), f2tf32(vb1.w));
        }
        __syncthreads();
        buf ^= 1;
    }

    // ---- epilogue ----
    #pragma unroll
    for (int mt = 0; mt < 2; mt++) {
        int r0 = crow + wm + mt * 16 + g;
        int r1 = r0 + 8;
        #pragma unroll
        for (int nt = 0; nt < 8; nt++) {
            int c = ccol + wn + nt * 8 + tig * 2;
            if (r0 < NN)
                *(float2*)(C + (size_t)r0 * 512 + c) = make_float2(acc[mt][nt][0], acc[mt][nt][1]);
            if (r1 < NN)
                *(float2*)(C + (size_t)r1 * 512 + c) = make_float2(acc[mt][nt][2], acc[mt][nt][3]);
        }
    }
}

// ---------------- aggregation: out[i] = (sum_{e:dst=i} h[src]*dis[src] + h[i]*dis[i]) * dis[i] + bias
// edge loop unrolled x4, 2 accumulator chains -> MLP ~4-8, halved FMA RAW chain
__global__ __launch_bounds__(128) void k_agg(const float* __restrict__ bias,
                                             float* __restrict__ out) {
    int node = blockIdx.x;
    int t = threadIdx.x;
    float di = g_dis[node];
    const float4* hp = reinterpret_cast<const float4*>(g_h);
    float4 v = hp[node * 128 + t];
    float4 a0, a1;
    a0.x = v.x * di; a0.y = v.y * di; a0.z = v.z * di; a0.w = v.w * di;
    a1.x = 0.f; a1.y = 0.f; a1.z = 0.f; a1.w = 0.f;
    const int beg = g_rowptr[node], end = g_rowptr[node + 1];
    int e = beg;
    for (; e + 4 <= end; e += 4) {
        int   s0 = g_col[e],     s1 = g_col[e + 1];
        int   s2 = g_col[e + 2], s3 = g_col[e + 3];
        float w0 = g_dis[s0], w1 = g_dis[s1], w2 = g_dis[s2], w3 = g_dis[s3];
        float4 u0 = hp[s0 * 128 + t];
        float4 u1 = hp[s1 * 128 + t];
        float4 u2 = hp[s2 * 128 + t];
        float4 u3 = hp[s3 * 128 + t];
        a0.x = fmaf(u0.x, w0, a0.x); a0.y = fmaf(u0.y, w0, a0.y);
        a0.z = fmaf(u0.z, w0, a0.z); a0.w = fmaf(u0.w, w0, a0.w);
        a1.x = fmaf(u1.x, w1, a1.x); a1.y = fmaf(u1.y, w1, a1.y);
        a1.z = fmaf(u1.z, w1, a1.z); a1.w = fmaf(u1.w, w1, a1.w);
        a0.x = fmaf(u2.x, w2, a0.x); a0.y = fmaf(u2.y, w2, a0.y);
        a0.z = fmaf(u2.z, w2, a0.z); a0.w = fmaf(u2.w, w2, a0.w);
        a1.x = fmaf(u3.x, w3, a1.x); a1.y = fmaf(u3.y, w3, a1.y);
        a1.z = fmaf(u3.z, w3, a1.z); a1.w = fmaf(u3.w, w3, a1.w);
    }
    for (; e < end; ++e) {
        int s = g_col[e];
        float w = g_dis[s];
        float4 u = hp[s * 128 + t];
        a0.x = fmaf(u.x, w, a0.x); a0.y = fmaf(u.y, w, a0.y);
        a0.z = fmaf(u.z, w, a0.z); a0.w = fmaf(u.w, w, a0.w);
    }
    a0.x += a1.x; a0.y += a1.y; a0.z += a1.z; a0.w += a1.w;
    float4 bb = reinterpret_cast<const float4*>(bias)[t];
    float4 o;
    o.x = fmaf(a0.x, di, bb.x);
    o.y = fmaf(a0.y, di, bb.y);
    o.z = fmaf(a0.z, di, bb.z);
    o.w = fmaf(a0.w, di, bb.w);
    reinterpret_cast<float4*>(out)[node * 128 + t] = o;
}

// ---------------- BatchNorm (training stats), deterministic 2-pass ----------------
// float4-vectorized: 128 threads x 4 features; per-feature accumulation order
// identical to scalar version -> bitwise-identical stats
__global__ __launch_bounds__(128) void k_bn_partial(const float* __restrict__ src) {
    int f4 = threadIdx.x;           // feature group (4 floats)
    int b  = blockIdx.x;
    float4 s = make_float4(0.f, 0.f, 0.f, 0.f);
    float4 q = make_float4(0.f, 0.f, 0.f, 0.f);
    const float4* sp = reinterpret_cast<const float4*>(src);
    for (int r = b; r < NN; r += NPB) {
        float4 v = sp[(size_t)r * 128 + f4];
        s.x += v.x; s.y += v.y; s.z += v.z; s.w += v.w;
        q.x = fmaf(v.x, v.x, q.x); q.y = fmaf(v.y, v.y, q.y);
        q.z = fmaf(v.z, v.z, q.z); q.w = fmaf(v.w, v.w, q.w);
    }
    reinterpret_cast<float4*>(g_psum)[b * 128 + f4] = s;
    reinterpret_cast<float4*>(g_psq )[b * 128 + f4] = q;
}

__global__ __launch_bounds__(256) void k_bn_final(const float* __restrict__ gamma,
                                                  const float* __restrict__ beta,
                                                  float* __restrict__ scale,
                                                  float* __restrict__ shift) {
    int f = blockIdx.x;
    int t = threadIdx.x;
    __shared__ float ss[256], sq[256];
    float s = 0.f, q = 0.f;
    for (int i = t; i < NPB; i += 256) {
        s += g_psum[i * DIM + f];
        q += g_psq [i * DIM + f];
    }
    ss[t] = s; sq[t] = q;
    __syncthreads();
    for (int off = 128; off > 0; off >>= 1) {
        if (t < off) { ss[t] += ss[t + off]; sq[t] += sq[t + off]; }
        __syncthreads();
    }
    if (t == 0) {
        float mean = ss[0] / (float)NN;
        float var  = sq[0] / (float)NN - mean * mean;
        float rstd = rsqrtf(var + BN_EPS);
        float sc = gamma[f] * rstd;
        scale[f] = sc;
        shift[f] = beta[f] - mean * sc;
    }
}

// ---------------- fused: lazy-BN JK-max + classifier GEMM + log_softmax ----------------
__global__ __launch_bounds__(256) void k_cls(const float* __restrict__ Wf,
                                             const float* __restrict__ bf,
                                             float* __restrict__ out) {
    __shared__ float As[16][64];
    __shared__ float Bs[16][NOUT];
    __shared__ float Ls[64][41];
    __shared__ float Lm[64], Ll[64];
    const int tid = threadIdx.x;
    const int rowbase = blockIdx.x * 64;
    const int row  = tid & 63;
    const int colg = tid >> 6;
    const int lrow = tid >> 2;
    const int lkq  = (tid & 3) << 2;

    float acc[10];
    #pragma unroll
    for (int j = 0; j < 10; j++) acc[j] = __ldg(bf + colg * 10 + j);

    for (int k0 = 0; k0 < DIM; k0 += 16) {
        {
            int r = rowbase + lrow;
            float4 v = make_float4(0.f, 0.f, 0.f, 0.f);
            if (r < NN) {
                size_t off = ((size_t)r * DIM + k0 + lkq) >> 2;
                int kf4 = (k0 + lkq) >> 2;
                float4 a = reinterpret_cast<const float4*>(g_agg1)[off];
                float4 b = reinterpret_cast<const float4*>(g_agg2)[off];
                float4 c = reinterpret_cast<const float4*>(g_agg3)[off];
                a = bnrelu4(a, reinterpret_cast<const float4*>(g_sc1)[kf4],
                               reinterpret_cast<const float4*>(g_sh1)[kf4]);
                b = bnrelu4(b, reinterpret_cast<const float4*>(g_sc2)[kf4],
                               reinterpret_cast<const float4*>(g_sh2)[kf4]);
                v.x = fmaxf(fmaxf(a.x, b.x), c.x);
                v.y = fmaxf(fmaxf(a.y, b.y), c.y);
                v.z = fmaxf(fmaxf(a.z, b.z), c.z);
                v.w = fmaxf(fmaxf(a.w, b.w), c.w);
            }
            As[lkq + 0][lrow] = v.x;
            As[lkq + 1][lrow] = v.y;
            As[lkq + 2][lrow] = v.z;
            As[lkq + 3][lrow] = v.w;
        }
        for (int i = tid; i < 16 * NOUT; i += 256) {
            int k = i / NOUT, c = i % NOUT;
            Bs[k][c] = Wf[(size_t)(k0 + k) * NOUT + c];
        }
        __syncthreads();
        #pragma unroll
        for (int k = 0; k < 16; k++) {
            float a = As[k][row];
            #pragma unroll
            for (int j = 0; j < 10; j++)
                acc[j] = fmaf(a, Bs[k][colg * 10 + j], acc[j]);
        }
        __syncthreads();
    }

    #pragma unroll
    for (int j = 0; j < 10; j++) Ls[row][colg * 10 + j] = acc[j];
    __syncthreads();

    if (tid < 64) {
        float m = -INFINITY;
        #pragma unroll
        for (int o = 0; o < NOUT; o++) m = fmaxf(m, Ls[tid][o]);
        float s = 0.f;
        #pragma unroll
        for (int o = 0; o < NOUT; o++) s += expf(Ls[tid][o] - m);
        Lm[tid] = m;
        Ll[tid] = logf(s);
    }
    __syncthreads();

    int r = rowbase + row;
    if (r < NN) {
        float ml = Lm[row] + Ll[row];
        #pragma unroll
        for (int j = 0; j < 10; j++)
            out[(size_t)r * NOUT + colg * 10 + j] = Ls[row][colg * 10 + j] - ml;
    }
}

// ---------------- launcher ----------------
extern "C" void kernel_launch(void* const* d_in, const int* in_sizes, int n_in,
                              void* d_out, int out_size) {
    const float* x   = (const float*)d_in[0];
    const int*   ei  = (const int*)  d_in[1];   // [2, E]: row0 src, row1 dst
    const float* W1  = (const float*)d_in[2];
    const float* b1  = (const float*)d_in[3];
    const float* g1  = (const float*)d_in[4];
    const float* be1 = (const float*)d_in[5];
    const float* W2  = (const float*)d_in[6];
    const float* b2  = (const float*)d_in[7];
    const float* g2  = (const float*)d_in[8];
    const float* be2 = (const float*)d_in[9];
    const float* W3  = (const float*)d_in[10];
    const float* b3  = (const float*)d_in[11];
    const float* Wf  = (const float*)d_in[12];
    const float* bf  = (const float*)d_in[13];
    float* out = (float*)d_out;

    const int* src = ei;
    const int* dst = ei + NE;

    // ALL device-scratch pointers crossing the launch boundary must come from
    // cudaGetSymbolAddress (host-code `g_xxx` decays to the host shadow!).
    float *p_h, *p_agg1, *p_agg2, *p_agg3, *p_sc1, *p_sh1, *p_sc2, *p_sh2;
    cudaGetSymbolAddress((void**)&p_h,    g_h);
    cudaGetSymbolAddress((void**)&p_agg1, g_agg1);
    cudaGetSymbolAddress((void**)&p_agg2, g_agg2);
    cudaGetSymbolAddress((void**)&p_agg3, g_agg3);
    cudaGetSymbolAddress((void**)&p_sc1,  g_sc1);
    cudaGetSymbolAddress((void**)&p_sh1,  g_sh1);
    cudaGetSymbolAddress((void**)&p_sc2,  g_sc2);
    cudaGetSymbolAddress((void**)&p_sh2,  g_sh2);

    dim3 gemm_grid(4, (NN + 127) / 128);

    // graph preprocessing (per-launch, deterministic work)
    k_zero_cnt<<<(NN + 255) / 256, 256>>>();
    k_count<<<(NE + 255) / 256, 256>>>(dst);
    k_scan<<<1, 1024>>>();
    k_fill<<<(NE + 255) / 256, 256>>>(src, dst);
    k_sortadj<<<(NN + 255) / 256, 256>>>();   // determinize adjacency ordering

    // layer 1
    k_gemm_tf32<0><<<gemm_grid, 256>>>(x, W1, p_h, nullptr, nullptr);
    k_agg<<<NN, 128>>>(b1, p_agg1);
    k_bn_partial<<<NPB, 128>>>(p_agg1);
    k_bn_final<<<DIM, 256>>>(g1, be1, p_sc1, p_sh1);

    // layer 2 (A = lazy bn+relu of agg1)
    k_gemm_tf32<1><<<gemm_grid, 256>>>(p_agg1, W2, p_h, p_sc1, p_sh1);
    k_agg<<<NN, 128>>>(b2, p_agg2);
    k_bn_partial<<<NPB, 128>>>(p_agg2);
    k_bn_final<<<DIM, 256>>>(g2, be2, p_sc2, p_sh2);

    // layer 3 (A = lazy bn+relu of agg2; no BN after)
    k_gemm_tf32<1><<<gemm_grid, 256>>>(p_agg2, W3, p_h, p_sc2, p_sh2);
    k_agg<<<NN, 128>>>(b3, p_agg3);

    // fused lazy-BN JK-max + classifier + log_softmax
    k_cls<<<(NN + 63) / 64, 256>>>(Wf, bf, out);

    (void)in_sizes; (void)n_in; (void)out_size;
}

// round 14
// speedup vs baseline: 1.0094x; 1.0094x over previous
#include <cuda_runtime.h>
#include <math.h>
#include <stdint.h>

#define NN   50000
#define NE   800000
#define DIM  512
#define NOUT 40
#define BN_EPS 1e-5f
#define NPB  512   // BN partial blocks

// ---------------- device scratch (module-static, allowed) ----------------
__device__ __align__(16) int   g_cnt[NN];
__device__ __align__(16) int   g_fill[NN];
__device__ __align__(16) int   g_rowptr[NN + 1];
__device__ __align__(16) float g_dis[NN];
__device__ __align__(16) int   g_col[NE];
__device__ __align__(16) float g_h   [NN * DIM];   // GEMM output
__device__ __align__(16) float g_agg1[NN * DIM];   // raw agg, layer 1
__device__ __align__(16) float g_agg2[NN * DIM];   // raw agg, layer 2
__device__ __align__(16) float g_agg3[NN * DIM];   // raw agg, layer 3 (= x3)
__device__ __align__(16) float g_psum[NPB * DIM];
__device__ __align__(16) float g_psq [NPB * DIM];
__device__ __align__(16) float g_sc1[DIM], g_sh1[DIM];
__device__ __align__(16) float g_sc2[DIM], g_sh2[DIM];

// ---------------- graph preprocessing ----------------
__global__ void k_zero_cnt() {
    int i = blockIdx.x * blockDim.x + threadIdx.x;
    if (i < NN) { g_cnt[i] = 0; g_fill[i] = 0; }
}

__global__ void k_count(const int* __restrict__ dst) {
    int e = blockIdx.x * blockDim.x + threadIdx.x;
    if (e < NE) atomicAdd(&g_cnt[dst[e]], 1);
}

// single-block inclusive scan -> rowptr, and dis = rsqrt(deg) with self-loop
__global__ __launch_bounds__(1024) void k_scan() {
    __shared__ int warp_sums[32];
    __shared__ int s_running;
    const int tid  = threadIdx.x;
    const int lane = tid & 31;
    const int wid  = tid >> 5;
    if (tid == 0) { g_rowptr[0] = 0; s_running = 0; }
    __syncthreads();
    for (int base = 0; base < NN; base += 1024) {
        int i = base + tid;
        int v = (i < NN) ? g_cnt[i] : 0;
        if (i < NN) g_dis[i] = rsqrtf((float)(v + 1));  // +1 self-loop
        int x = v;
        #pragma unroll
        for (int off = 1; off < 32; off <<= 1) {
            int y = __shfl_up_sync(0xFFFFFFFFu, x, off);
            if (lane >= off) x += y;
        }
        if (lane == 31) warp_sums[wid] = x;
        __syncthreads();
        if (wid == 0) {
            int w = warp_sums[lane];
            #pragma unroll
            for (int off = 1; off < 32; off <<= 1) {
                int y = __shfl_up_sync(0xFFFFFFFFu, w, off);
                if (lane >= off) w += y;
            }
            warp_sums[lane] = w;
        }
        __syncthreads();
        int warp_off = (wid > 0) ? warp_sums[wid - 1] : 0;
        int incl = x + warp_off + s_running;
        if (i < NN) g_rowptr[i + 1] = incl;
        __syncthreads();
        if (tid == 1023) s_running = incl;
        __syncthreads();
    }
}

__global__ void k_fill(const int* __restrict__ src, const int* __restrict__ dst) {
    int e = blockIdx.x * blockDim.x + threadIdx.x;
    if (e < NE) {
        int d = dst[e];
        int p = g_rowptr[d] + atomicAdd(&g_fill[d], 1);
        g_col[p] = src[e];
    }
}

// per-node insertion sort -> deterministic adjacency regardless of atomic order
__global__ void k_sortadj() {
    int n = blockIdx.x * blockDim.x + threadIdx.x;
    if (n >= NN) return;
    int beg = g_rowptr[n], end = g_rowptr[n + 1];
    for (int i = beg + 1; i < end; ++i) {
        int key = g_col[i];
        int j = i - 1;
        while (j >= beg && g_col[j] > key) { g_col[j + 1] = g_col[j]; --j; }
        g_col[j + 1] = key;
    }
}

// ---------------- tf32 helpers ----------------
// NOTE: no cvt needed. mma.tf32 reads only the top-19 bits of each .b32 operand,
// so raw fp32 bits = truncation-rounding. Saves 24 CVT issues/thread/tile.
__device__ __forceinline__ void mma_tf32(float& c0, float& c1, float& c2, float& c3,
                                         float a0, float a1, float a2, float a3,
                                         float b0, float b1) {
    asm volatile(
        "mma.sync.aligned.m16n8k8.row.col.f32.tf32.tf32.f32 "
        "{%0,%1,%2,%3}, {%4,%5,%6,%7}, {%8,%9}, {%0,%1,%2,%3};"
        : "+f"(c0), "+f"(c1), "+f"(c2), "+f"(c3)
        : "r"(__float_as_uint(a0)), "r"(__float_as_uint(a1)),
          "r"(__float_as_uint(a2)), "r"(__float_as_uint(a3)),
          "r"(__float_as_uint(b0)), "r"(__float_as_uint(b1)));
}

__device__ __forceinline__ float4 bnrelu4(float4 v, float4 sc, float4 sh) {
    v.x = fmaxf(fmaf(v.x, sc.x, sh.x), 0.f);
    v.y = fmaxf(fmaf(v.y, sc.y, sh.y), 0.f);
    v.z = fmaxf(fmaf(v.z, sc.z, sh.z), 0.f);
    v.w = fmaxf(fmaf(v.w, sc.w, sh.w), 0.f);
    return v;
}

// ---------------- tf32 tensor-core GEMM: C[M,512] = f(A)[M,512] @ B[512,512] ----------------
// BN template: f(A) = relu(A*sc + sh) applied at load (per-feature = per-k)
// block 128x128, Ktile 16, double-buffered; 8 warps, each 32(M) x 64(N)
#define SPAD 136
template <int BN>
__global__ __launch_bounds__(256) void k_gemm_tf32(const float* __restrict__ A,
                                                   const float* __restrict__ B,
                                                   float* __restrict__ C,
                                                   const float* __restrict__ sc,
                                                   const float* __restrict__ sh) {
    __shared__ float As[2][16][SPAD];   // [k][m]
    __shared__ float Bs[2][16][SPAD];   // [k][n]
    const int tid  = threadIdx.x;
    const int crow = blockIdx.y * 128;
    const int ccol = blockIdx.x * 128;

    const int warp = tid >> 5;
    const int lane = tid & 31;
    const int g    = lane >> 2;      // groupID 0..7
    const int tig  = lane & 3;       // thread-in-group 0..3
    const int wm   = (warp & 3) * 32;  // warp M offset 0..96
    const int wn   = (warp >> 2) * 64; // warp N offset 0,64

    const int aRow = tid >> 1;             // 0..127
    const int aK   = (tid & 1) * 8;        // 0 or 8
    const int bRow = tid >> 4;             // 0..15
    const int bC   = (tid & 15) * 4;       // 0..60, +64 for second

    float acc[2][8][4];
    #pragma unroll
    for (int mt = 0; mt < 2; mt++)
        #pragma unroll
        for (int nt = 0; nt < 8; nt++)
            #pragma unroll
            for (int i = 0; i < 4; i++) acc[mt][nt][i] = 0.f;

    const float4 z4 = make_float4(0.f, 0.f, 0.f, 0.f);
    float4 va0, va1, vb0, vb1;

    // ---- prologue: load K-tile 0 ----
    {
        int r = crow + aRow;
        va0 = (r < NN) ? *(const float4*)(A + (size_t)r * 512 + 0 + aK)     : z4;
        va1 = (r < NN) ? *(const float4*)(A + (size_t)r * 512 + 0 + aK + 4) : z4;
        if (BN) {
            va0 = bnrelu4(va0, *(const float4*)(sc + aK),     *(const float4*)(sh + aK));
            va1 = bnrelu4(va1, *(const float4*)(sc + aK + 4), *(const float4*)(sh + aK + 4));
        }
        vb0 = *(const float4*)(B + (size_t)(0 + bRow) * 512 + ccol + bC);
        vb1 = *(const float4*)(B + (size_t)(0 + bRow) * 512 + ccol + bC + 64);
        As[0][aK + 0][aRow] = va0.x;
        As[0][aK + 1][aRow] = va0.y;
        As[0][aK + 2][aRow] = va0.z;
        As[0][aK + 3][aRow] = va0.w;
        As[0][aK + 4][aRow] = va1.x;
        As[0][aK + 5][aRow] = va1.y;
        As[0][aK + 6][aRow] = va1.z;
        As[0][aK + 7][aRow] = va1.w;
        *(float4*)&Bs[0][bRow][bC]      = vb0;
        *(float4*)&Bs[0][bRow][bC + 64] = vb1;
    }
    __syncthreads();

    int buf = 0;
    for (int t = 0; t < 32; ++t) {
        if (t < 31) {
            const int k0 = (t + 1) * 16;
            int r = crow + aRow;
            va0 = (r < NN) ? *(const float4*)(A + (size_t)r * 512 + k0 + aK)     : z4;
            va1 = (r < NN) ? *(const float4*)(A + (size_t)r * 512 + k0 + aK + 4) : z4;
            if (BN) {
                va0 = bnrelu4(va0, *(const float4*)(sc + k0 + aK),     *(const float4*)(sh + k0 + aK));
                va1 = bnrelu4(va1, *(const float4*)(sc + k0 + aK + 4), *(const float4*)(sh + k0 + aK + 4));
            }
            vb0 = *(const float4*)(B + (size_t)(k0 + bRow) * 512 + ccol + bC);
            vb1 = *(const float4*)(B + (size_t)(k0 + bRow) * 512 + ccol + bC + 64);
        }
        #pragma unroll
        for (int kk = 0; kk < 16; kk += 8) {
            float af[2][4];
            #pragma unroll
            for (int mt = 0; mt < 2; mt++) {
                int m = wm + mt * 16 + g;
                af[mt][0] = As[buf][kk + tig]    [m];
                af[mt][1] = As[buf][kk + tig]    [m + 8];
                af[mt][2] = As[buf][kk + tig + 4][m];
                af[mt][3] = As[buf][kk + tig + 4][m + 8];
            }
            float bfr[8][2];
            #pragma unroll
            for (int nt = 0; nt < 8; nt++) {
                int n = wn + nt * 8 + g;
                bfr[nt][0] = Bs[buf][kk + tig]    [n];
                bfr[nt][1] = Bs[buf][kk + tig + 4][n];
            }
            #pragma unroll
            for (int mt = 0; mt < 2; mt++)
                #pragma unroll
                for (int nt = 0; nt < 8; nt++)
                    mma_tf32(acc[mt][nt][0], acc[mt][nt][1], acc[mt][nt][2], acc[mt][nt][3],
                             af[mt][0], af[mt][1], af[mt][2], af[mt][3],
                             bfr[nt][0], bfr[nt][1]);
        }
        if (t < 31) {
            int nb = buf ^ 1;
            As[nb][aK + 0][aRow] = va0.x;
            As[nb][aK + 1][aRow] = va0.y;
            As[nb][aK + 2][aRow] = va0.z;
            As[nb][aK + 3][aRow] = va0.w;
            As[nb][aK + 4][aRow] = va1.x;
            As[nb][aK + 5][aRow] = va1.y;
            As[nb][aK + 6][aRow] = va1.z;
            As[nb][aK + 7][aRow] = va1.w;
            *(float4*)&Bs[nb][bRow][bC]      = vb0;
            *(float4*)&Bs[nb][bRow][bC + 64] = vb1;
        }
        __syncthreads();
        buf ^= 1;
    }

    // ---- epilogue ----
    #pragma unroll
    for (int mt = 0; mt < 2; mt++) {
        int r0 = crow + wm + mt * 16 + g;
        int r1 = r0 + 8;
        #pragma unroll
        for (int nt = 0; nt < 8; nt++) {
            int c = ccol + wn + nt * 8 + tig * 2;
            if (r0 < NN)
                *(float2*)(C + (size_t)r0 * 512 + c) = make_float2(acc[mt][nt][0], acc[mt][nt][1]);
            if (r1 < NN)
                *(float2*)(C + (size_t)r1 * 512 + c) = make_float2(acc[mt][nt][2], acc[mt][nt][3]);
        }
    }
}

// ---------------- aggregation: out[i] = (sum_{e:dst=i} h[src]*dis[src] + h[i]*dis[i]) * dis[i] + bias
// edge loop unrolled x8, 2 accumulator chains -> MLP ~8
__global__ __launch_bounds__(128) void k_agg(const float* __restrict__ bias,
                                             float* __restrict__ out) {
    int node = blockIdx.x;
    int t = threadIdx.x;
    float di = g_dis[node];
    const float4* hp = reinterpret_cast<const float4*>(g_h);
    float4 v = hp[node * 128 + t];
    float4 a0, a1;
    a0.x = v.x * di; a0.y = v.y * di; a0.z = v.z * di; a0.w = v.w * di;
    a1.x = 0.f; a1.y = 0.f; a1.z = 0.f; a1.w = 0.f;
    const int beg = g_rowptr[node], end = g_rowptr[node + 1];
    int e = beg;
    for (; e + 8 <= end; e += 8) {
        int s0 = g_col[e],     s1 = g_col[e + 1], s2 = g_col[e + 2], s3 = g_col[e + 3];
        int s4 = g_col[e + 4], s5 = g_col[e + 5], s6 = g_col[e + 6], s7 = g_col[e + 7];
        float w0 = g_dis[s0], w1 = g_dis[s1], w2 = g_dis[s2], w3 = g_dis[s3];
        float w4 = g_dis[s4], w5 = g_dis[s5], w6 = g_dis[s6], w7 = g_dis[s7];
        float4 u0 = hp[s0 * 128 + t];
        float4 u1 = hp[s1 * 128 + t];
        float4 u2 = hp[s2 * 128 + t];
        float4 u3 = hp[s3 * 128 + t];
        float4 u4 = hp[s4 * 128 + t];
        float4 u5 = hp[s5 * 128 + t];
        float4 u6 = hp[s6 * 128 + t];
        float4 u7 = hp[s7 * 128 + t];
        a0.x = fmaf(u0.x, w0, a0.x); a0.y = fmaf(u0.y, w0, a0.y);
        a0.z = fmaf(u0.z, w0, a0.z); a0.w = fmaf(u0.w, w0, a0.w);
        a1.x = fmaf(u1.x, w1, a1.x); a1.y = fmaf(u1.y, w1, a1.y);
        a1.z = fmaf(u1.z, w1, a1.z); a1.w = fmaf(u1.w, w1, a1.w);
        a0.x = fmaf(u2.x, w2, a0.x); a0.y = fmaf(u2.y, w2, a0.y);
        a0.z = fmaf(u2.z, w2, a0.z); a0.w = fmaf(u2.w, w2, a0.w);
        a1.x = fmaf(u3.x, w3, a1.x); a1.y = fmaf(u3.y, w3, a1.y);
        a1.z = fmaf(u3.z, w3, a1.z); a1.w = fmaf(u3.w, w3, a1.w);
        a0.x = fmaf(u4.x, w4, a0.x); a0.y = fmaf(u4.y, w4, a0.y);
        a0.z = fmaf(u4.z, w4, a0.z); a0.w = fmaf(u4.w, w4, a0.w);
        a1.x = fmaf(u5.x, w5, a1.x); a1.y = fmaf(u5.y, w5, a1.y);
        a1.z = fmaf(u5.z, w5, a1.z); a1.w = fmaf(u5.w, w5, a1.w);
        a0.x = fmaf(u6.x, w6, a0.x); a0.y = fmaf(u6.y, w6, a0.y);
        a0.z = fmaf(u6.z, w6, a0.z); a0.w = fmaf(u6.w, w6, a0.w);
        a1.x = fmaf(u7.x, w7, a1.x); a1.y = fmaf(u7.y, w7, a1.y);
        a1.z = fmaf(u7.z, w7, a1.z); a1.w = fmaf(u7.w, w7, a1.w);
    }
    for (; e < end; ++e) {
        int s = g_col[e];
        float w = g_dis[s];
        float4 u = hp[s * 128 + t];
        a0.x = fmaf(u.x, w, a0.x); a0.y = fmaf(u.y, w, a0.y);
        a0.z = fmaf(u.z, w, a0.z); a0.w = fmaf(u.w, w, a0.w);
    }
    a0.x += a1.x; a0.y += a1.y; a0.z += a1.z; a0.w += a1.w;
    float4 bb = reinterpret_cast<const float4*>(bias)[t];
    float4 o;
    o.x = fmaf(a0.x, di, bb.x);
    o.y = fmaf(a0.y, di, bb.y);
    o.z = fmaf(a0.z, di, bb.z);
    o.w = fmaf(a0.w, di, bb.w);
    reinterpret_cast<float4*>(out)[node * 128 + t] = o;
}

// ---------------- BatchNorm (training stats), deterministic 2-pass ----------------
__global__ __launch_bounds__(128) void k_bn_partial(const float* __restrict__ src) {
    int f4 = threadIdx.x;
    int b  = blockIdx.x;
    float4 s = make_float4(0.f, 0.f, 0.f, 0.f);
    float4 q = make_float4(0.f, 0.f, 0.f, 0.f);
    const float4* sp = reinterpret_cast<const float4*>(src);
    for (int r = b; r < NN; r += NPB) {
        float4 v = sp[(size_t)r * 128 + f4];
        s.x += v.x; s.y += v.y; s.z += v.z; s.w += v.w;
        q.x = fmaf(v.x, v.x, q.x); q.y = fmaf(v.y, v.y, q.y);
        q.z = fmaf(v.z, v.z, q.z); q.w = fmaf(v.w, v.w, q.w);
    }
    reinterpret_cast<float4*>(g_psum)[b * 128 + f4] = s;
    reinterpret_cast<float4*>(g_psq )[b * 128 + f4] = q;
}

__global__ __launch_bounds__(256) void k_bn_final(const float* __restrict__ gamma,
                                                  const float* __restrict__ beta,
                                                  float* __restrict__ scale,
                                                  float* __restrict__ shift) {
    int f = blockIdx.x;
    int t = threadIdx.x;
    __shared__ float ss[256], sq[256];
    float s = 0.f, q = 0.f;
    for (int i = t; i < NPB; i += 256) {
        s += g_psum[i * DIM + f];
        q += g_psq [i * DIM + f];
    }
    ss[t] = s; sq[t] = q;
    __syncthreads();
    for (int off = 128; off > 0; off >>= 1) {
        if (t < off) { ss[t] += ss[t + off]; sq[t] += sq[t + off]; }
        __syncthreads();
    }
    if (t == 0) {
        float mean = ss[0] / (float)NN;
        float var  = sq[0] / (float)NN - mean * mean;
        float rstd = rsqrtf(var + BN_EPS);
        float sc = gamma[f] * rstd;
        scale[f] = sc;
        shift[f] = beta[f] - mean * sc;
    }
}

// ---------------- fused: lazy-BN JK-max + classifier GEMM + log_softmax ----------------
__global__ __launch_bounds__(256) void k_cls(const float* __restrict__ Wf,
                                             const float* __restrict__ bf,
                                             float* __restrict__ out) {
    __shared__ float As[16][64];
    __shared__ float Bs[16][NOUT];
    __shared__ float Ls[64][41];
    __shared__ float Lm[64], Ll[64];
    const int tid = threadIdx.x;
    const int rowbase = blockIdx.x * 64;
    const int row  = tid & 63;
    const int colg = tid >> 6;
    const int lrow = tid >> 2;
    const int lkq  = (tid & 3) << 2;

    float acc[10];
    #pragma unroll
    for (int j = 0; j < 10; j++) acc[j] = __ldg(bf + colg * 10 + j);

    for (int k0 = 0; k0 < DIM; k0 += 16) {
        {
            int r = rowbase + lrow;
            float4 v = make_float4(0.f, 0.f, 0.f, 0.f);
            if (r < NN) {
                size_t off = ((size_t)r * DIM + k0 + lkq) >> 2;
                int kf4 = (k0 + lkq) >> 2;
                float4 a = reinterpret_cast<const float4*>(g_agg1)[off];
                float4 b = reinterpret_cast<const float4*>(g_agg2)[off];
                float4 c = reinterpret_cast<const float4*>(g_agg3)[off];
                a = bnrelu4(a, reinterpret_cast<const float4*>(g_sc1)[kf4],
                               reinterpret_cast<const float4*>(g_sh1)[kf4]);
                b = bnrelu4(b, reinterpret_cast<const float4*>(g_sc2)[kf4],
                               reinterpret_cast<const float4*>(g_sh2)[kf4]);
                v.x = fmaxf(fmaxf(a.x, b.x), c.x);
                v.y = fmaxf(fmaxf(a.y, b.y), c.y);
                v.z = fmaxf(fmaxf(a.z, b.z), c.z);
                v.w = fmaxf(fmaxf(a.w, b.w), c.w);
            }
            As[lkq + 0][lrow] = v.x;
            As[lkq + 1][lrow] = v.y;
            As[lkq + 2][lrow] = v.z;
            As[lkq + 3][lrow] = v.w;
        }
        for (int i = tid; i < 16 * NOUT; i += 256) {
            int k = i / NOUT, c = i % NOUT;
            Bs[k][c] = Wf[(size_t)(k0 + k) * NOUT + c];
        }
        __syncthreads();
        #pragma unroll
        for (int k = 0; k < 16; k++) {
            float a = As[k][row];
            #pragma unroll
            for (int j = 0; j < 10; j++)
                acc[j] = fmaf(a, Bs[k][colg * 10 + j], acc[j]);
        }
        __syncthreads();
    }

    #pragma unroll
    for (int j = 0; j < 10; j++) Ls[row][colg * 10 + j] = acc[j];
    __syncthreads();

    if (tid < 64) {
        float m = -INFINITY;
        #pragma unroll
        for (int o = 0; o < NOUT; o++) m = fmaxf(m, Ls[tid][o]);
        float s = 0.f;
        #pragma unroll
        for (int o = 0; o < NOUT; o++) s += expf(Ls[tid][o] - m);
        Lm[tid] = m;
        Ll[tid] = logf(s);
    }
    __syncthreads();

    int r = rowbase + row;
    if (r < NN) {
        float ml = Lm[row] + Ll[row];
        #pragma unroll
        for (int j = 0; j < 10; j++)
            out[(size_t)r * NOUT + colg * 10 + j] = Ls[row][colg * 10 + j] - ml;
    }
}

// ---------------- launcher ----------------
extern "C" void kernel_launch(void* const* d_in, const int* in_sizes, int n_in,
                              void* d_out, int out_size) {
    const float* x   = (const float*)d_in[0];
    const int*   ei  = (const int*)  d_in[1];   // [2, E]: row0 src, row1 dst
    const float* W1  = (const float*)d_in[2];
    const float* b1  = (const float*)d_in[3];
    const float* g1  = (const float*)d_in[4];
    const float* be1 = (const float*)d_in[5];
    const float* W2  = (const float*)d_in[6];
    const float* b2  = (const float*)d_in[7];
    const float* g2  = (const float*)d_in[8];
    const float* be2 = (const float*)d_in[9];
    const float* W3  = (const float*)d_in[10];
    const float* b3  = (const float*)d_in[11];
    const float* Wf  = (const float*)d_in[12];
    const float* bf  = (const float*)d_in[13];
    float* out = (float*)d_out;

    const int* src = ei;
    const int* dst = ei + NE;

    float *p_h, *p_agg1, *p_agg2, *p_agg3, *p_sc1, *p_sh1, *p_sc2, *p_sh2;
    cudaGetSymbolAddress((void**)&p_h,    g_h);
    cudaGetSymbolAddress((void**)&p_agg1, g_agg1);
    cudaGetSymbolAddress((void**)&p_agg2, g_agg2);
    cudaGetSymbolAddress((void**)&p_agg3, g_agg3);
    cudaGetSymbolAddress((void**)&p_sc1,  g_sc1);
    cudaGetSymbolAddress((void**)&p_sh1,  g_sh1);
    cudaGetSymbolAddress((void**)&p_sc2,  g_sc2);
    cudaGetSymbolAddress((void**)&p_sh2,  g_sh2);

    dim3 gemm_grid(4, (NN + 127) / 128);

    // graph preprocessing (per-launch, deterministic work)
    k_zero_cnt<<<(NN + 255) / 256, 256>>>();
    k_count<<<(NE + 255) / 256, 256>>>(dst);
    k_scan<<<1, 1024>>>();
    k_fill<<<(NE + 255) / 256, 256>>>(src, dst);
    k_sortadj<<<(NN + 255) / 256, 256>>>();

    // layer 1
    k_gemm_tf32<0><<<gemm_grid, 256>>>(x, W1, p_h, nullptr, nullptr);
    k_agg<<<NN, 128>>>(b1, p_agg1);
    k_bn_partial<<<NPB, 128>>>(p_agg1);
    k_bn_final<<<DIM, 256>>>(g1, be1, p_sc1, p_sh1);

    // layer 2 (A = lazy bn+relu of agg1)
    k_gemm_tf32<1><<<gemm_grid, 256>>>(p_agg1, W2, p_h, p_sc1, p_sh1);
    k_agg<<<NN, 128>>>(b2, p_agg2);
    k_bn_partial<<<NPB, 128>>>(p_agg2);
    k_bn_final<<<DIM, 256>>>(g2, be2, p_sc2, p_sh2);

    // layer 3 (A = lazy bn+relu of agg2; no BN after)
    k_gemm_tf32<1><<<gemm_grid, 256>>>(p_agg2, W3, p_h, p_sc2, p_sh2);
    k_agg<<<NN, 128>>>(b3, p_agg3);

    // fused lazy-BN JK-max + classifier + log_softmax
    k_cls<<<(NN + 63) / 64, 256>>>(Wf, bf, out);

    (void)in_sizes; (void)n_in; (void)out_size;
}